// round 2
// baseline (speedup 1.0000x reference)
#include <cuda_runtime.h>
#include <math.h>

#define NPTS 4096
#define BITD 64
#define LLAB 10
#define RT   256
#define UPPERB 16.0f
// c = (1/right)*ln(yp/(99(1-yp))) with right=64/6, yp=0.5  -> -6*ln(99)/64
#define CONST_C    (-0.43079248594386178f)
#define CONST_AC   (-0.86158497188772356f)   // a*c, a = 2 exactly
#define CONST_BASE (0.0f)

// ---------------- device scratch ----------------
__device__ float    g_inner[(size_t)NPTS * NPTS];   // 64 MB
__device__ unsigned g_maskArr[NPTS];
__device__ unsigned g_Ybits[LLAB * (NPTS / 32)];    // per-label membership bitvectors
__device__ float2   g_rowout[NPTS];                 // (rowres, valid)
__device__ unsigned g_ctr;

// ---------------- helpers ----------------
__device__ __forceinline__ unsigned fkey(float f) {
    unsigned u = __float_as_uint(f);
    return u ^ (((unsigned)((int)u >> 31)) | 0x80000000u);  // monotonic float->uint
}
__device__ __forceinline__ float finv(unsigned k) {
    unsigned u = (k & 0x80000000u) ? (k ^ 0x80000000u) : ~k;
    return __uint_as_float(u);
}
__device__ __forceinline__ float softplusf(float x) {
    return fmaxf(x, 0.f) + __logf(1.f + __expf(-fabsf(x)));
}

__device__ __forceinline__ float blockReduceF(float v, float* sh) {
    int tid = threadIdx.x, lane = tid & 31, wid = tid >> 5;
    #pragma unroll
    for (int o = 16; o > 0; o >>= 1) v += __shfl_down_sync(0xffffffffu, v, o);
    if (lane == 0) sh[wid] = v;
    __syncthreads();
    if (tid == 0) {
        float s = 0.f;
        #pragma unroll
        for (int w = 0; w < RT / 32; w++) s += sh[w];
        sh[0] = s;
    }
    __syncthreads();
    v = sh[0];
    __syncthreads();
    return v;
}
__device__ __forceinline__ int blockReduceI(int v, int* sh) {
    int tid = threadIdx.x, lane = tid & 31, wid = tid >> 5;
    #pragma unroll
    for (int o = 16; o > 0; o >>= 1) v += __shfl_down_sync(0xffffffffu, v, o);
    if (lane == 0) sh[wid] = v;
    __syncthreads();
    if (tid == 0) {
        int s = 0;
        #pragma unroll
        for (int w = 0; w < RT / 32; w++) s += sh[w];
        sh[0] = s;
    }
    __syncthreads();
    v = sh[0];
    __syncthreads();
    return v;
}

// ---------------- kernel 0: label bitmasks + per-label bitvectors ----------------
__global__ void mask_kernel(const int* __restrict__ y) {
    int j = blockIdx.x * blockDim.x + threadIdx.x;   // 4096 threads
    unsigned m = 0;
    #pragma unroll
    for (int l = 0; l < LLAB; l++) m |= (y[j * LLAB + l] != 0 ? 1u : 0u) << l;
    g_maskArr[j] = m;
    int word = j >> 5, lane = j & 31;
    #pragma unroll
    for (int b = 0; b < LLAB; b++) {
        unsigned bal = __ballot_sync(0xffffffffu, (m >> b) & 1u);
        if (lane == 0) g_Ybits[b * (NPTS / 32) + word] = bal;
    }
    if (j == 0) g_ctr = 0;
}

// ---------------- kernel 1: inner = U @ V^T ----------------
// 128x128 tile, 256 threads, 8x8 micro-tile, smem K-major (transposed) so
// fragments load as LDS.128. K staged in halves of 32.
#define TKG  32
#define RPAD 132
__global__ void __launch_bounds__(256) gemm_kernel(const float* __restrict__ U,
                                                   const float* __restrict__ V) {
    __shared__ float As[TKG][RPAD];
    __shared__ float Bs[TKG][RPAD];
    int tid = threadIdx.x;
    int tx = tid & 15, ty = tid >> 4;          // 16x16 thread grid
    int brow = blockIdx.y * 128, bcol = blockIdx.x * 128;

    float acc[8][8];
    #pragma unroll
    for (int i = 0; i < 8; i++)
        #pragma unroll
        for (int j = 0; j < 8; j++) acc[i][j] = 0.f;

    for (int ks = 0; ks < BITD; ks += TKG) {
        #pragma unroll
        for (int q = 0; q < 4; q++) {
            int fid = q * 256 + tid;           // 0..1023 float4 slots
            int r   = fid >> 3;                // 0..127
            int k4  = (fid & 7) * 4;           // 0..28
            float4 a = *(const float4*)(U + (size_t)(brow + r) * BITD + ks + k4);
            As[k4 + 0][r] = a.x; As[k4 + 1][r] = a.y;
            As[k4 + 2][r] = a.z; As[k4 + 3][r] = a.w;
            float4 b = *(const float4*)(V + (size_t)(bcol + r) * BITD + ks + k4);
            Bs[k4 + 0][r] = b.x; Bs[k4 + 1][r] = b.y;
            Bs[k4 + 2][r] = b.z; Bs[k4 + 3][r] = b.w;
        }
        __syncthreads();
        #pragma unroll
        for (int k = 0; k < TKG; k++) {
            float ar[8], bc[8];
            *(float4*)(ar)     = *(const float4*)(&As[k][ty * 8]);
            *(float4*)(ar + 4) = *(const float4*)(&As[k][ty * 8 + 4]);
            *(float4*)(bc)     = *(const float4*)(&Bs[k][tx * 8]);
            *(float4*)(bc + 4) = *(const float4*)(&Bs[k][tx * 8 + 4]);
            #pragma unroll
            for (int i = 0; i < 8; i++)
                #pragma unroll
                for (int j = 0; j < 8; j++) acc[i][j] = fmaf(ar[i], bc[j], acc[i][j]);
        }
        __syncthreads();
    }
    #pragma unroll
    for (int i = 0; i < 8; i++) {
        int row = brow + ty * 8 + i;
        float* op = g_inner + (size_t)row * NPTS + bcol + tx * 8;
        float4 o0 = make_float4(acc[i][0], acc[i][1], acc[i][2], acc[i][3]);
        float4 o1 = make_float4(acc[i][4], acc[i][5], acc[i][6], acc[i][7]);
        *(float4*)(op)     = o0;
        *(float4*)(op + 4) = o1;
    }
}

// ---------------- rank locate within a histogram ----------------
// hist has 256*BPT bins; finds bin containing rank q (1-based) and remaining
// rank within that bin. Exactly one thread writes outBR. All-threads sync'd.
template<int BPT>
__device__ __forceinline__ void locate(const unsigned* hist, unsigned q,
                                       unsigned* wsum, unsigned* outBR) {
    int tid = threadIdx.x, lane = tid & 31, wid = tid >> 5;
    unsigned s = 0;
    int b0 = tid * BPT;
    #pragma unroll
    for (int t = 0; t < BPT; t++) s += hist[b0 + t];
    unsigned v = s;
    #pragma unroll
    for (int o = 1; o < 32; o <<= 1) {
        unsigned t = __shfl_up_sync(0xffffffffu, v, o);
        if (lane >= o) v += t;
    }
    if (lane == 31) wsum[wid] = v;
    __syncthreads();
    unsigned wb = 0;
    #pragma unroll
    for (int w = 0; w < RT / 32; w++) if (w < wid) wb += wsum[w];
    unsigned incl = wb + v, excl = incl - s;
    if (q > excl && q <= incl) {
        unsigned c = excl;
        #pragma unroll
        for (int t = 0; t < BPT; t++) {
            unsigned h = hist[b0 + t];
            if (q > c && q <= c + h) { outBR[0] = (unsigned)(b0 + t); outBR[1] = q - c; }
            c += h;
        }
    }
    __syncthreads();
}

// ---------------- kernel 2: per-row loss (+ fused final reduction) ----------------
__global__ void __launch_bounds__(RT) row_kernel(float* __restrict__ out) {
    __shared__ unsigned histS[2048], histD[2048];
    __shared__ unsigned wsum[RT / 32];
    __shared__ float    fsh[RT / 32];
    __shared__ int      ish[RT / 32];
    __shared__ unsigned brS[2], brD[2];
    __shared__ int      lastFlag;

    int tid = threadIdx.x, i = blockIdx.x;

    for (int t = tid; t < 2048; t += RT) { histS[t] = 0u; histD[t] = 0u; }

    // class bits for my 16 contiguous elements [tid*16, tid*16+16)
    unsigned mi = g_maskArr[i];
    unsigned cls = 0;
    const unsigned short* yb = (const unsigned short*)g_Ybits;
    #pragma unroll
    for (int b = 0; b < LLAB; b++) {
        unsigned w = (unsigned)yb[b * (NPTS / 16) + tid];
        cls |= w & (0u - ((mi >> b) & 1u));
    }

    // load my 16 values into registers
    const float* rowp = g_inner + (size_t)i * NPTS + tid * 16;
    float x[16];
    #pragma unroll
    for (int q = 0; q < 4; q++) {
        float4 f = *(const float4*)(rowp + q * 4);
        x[q * 4 + 0] = f.x; x[q * 4 + 1] = f.y;
        x[q * 4 + 2] = f.z; x[q * 4 + 3] = f.w;
    }
    __syncthreads();   // hist cleared

    // pass 1: class sums + top-11-bit histograms
    float sS = 0.f, sD = 0.f;
    #pragma unroll
    for (int e = 0; e < 16; e++) {
        unsigned kk = fkey(x[e]);
        if ((cls >> e) & 1u) { sS += x[e]; atomicAdd(&histS[kk >> 21], 1u); }
        else                 { sD += x[e]; atomicAdd(&histD[(~kk) >> 21], 1u); }
    }
    int ns = blockReduceI(__popc(cls), ish);
    sS = blockReduceF(sS, fsh);
    sD = blockReduceF(sD, fsh);
    int nd = NPTS - ns;

    int ks = (ns * 9) / 10, kd = (nd * 9) / 10;
    unsigned qS = (unsigned)(ns - ks), qD = (unsigned)(nd - kd);
    bool valid = (ns > 0) && (nd > 0);

    float rowres = 0.f;
    if (valid) {
        locate<8>(histS, qS, wsum, brS);
        locate<8>(histD, qD, wsum, brD);
        unsigned b1S = brS[0], r1S = brS[1];
        unsigned b1D = brD[0], r1D = brD[1];

        // pass 2: middle 11 bits
        for (int t = tid; t < 2048; t += RT) { histS[t] = 0u; histD[t] = 0u; }
        __syncthreads();
        #pragma unroll
        for (int e = 0; e < 16; e++) {
            unsigned kk = fkey(x[e]);
            if ((cls >> e) & 1u) {
                if ((kk >> 21) == b1S) atomicAdd(&histS[(kk >> 10) & 2047u], 1u);
            } else {
                unsigned kd2 = ~kk;
                if ((kd2 >> 21) == b1D) atomicAdd(&histD[(kd2 >> 10) & 2047u], 1u);
            }
        }
        __syncthreads();
        locate<8>(histS, r1S, wsum, brS);
        locate<8>(histD, r1D, wsum, brD);
        unsigned b2S = brS[0], r2S = brS[1];
        unsigned b2D = brD[0], r2D = brD[1];
        unsigned p22S = (b1S << 11) | b2S;
        unsigned p22D = (b1D << 11) | b2D;

        // pass 3: low 10 bits
        for (int t = tid; t < 2048; t += RT) { histS[t] = 0u; histD[t] = 0u; }
        __syncthreads();
        #pragma unroll
        for (int e = 0; e < 16; e++) {
            unsigned kk = fkey(x[e]);
            if ((cls >> e) & 1u) {
                if ((kk >> 10) == p22S) atomicAdd(&histS[kk & 1023u], 1u);
            } else {
                unsigned kd2 = ~kk;
                if ((kd2 >> 10) == p22D) atomicAdd(&histD[kd2 & 1023u], 1u);
            }
        }
        __syncthreads();
        locate<4>(histS, r2S, wsum, brS);
        locate<4>(histD, r2D, wsum, brD);
        unsigned TS = (p22S << 10) | brS[0];
        unsigned TD = (p22D << 10) | brD[0];

        // final: exact sums below thresholds (register-only scan)
        float sLS = 0.f, sLD = 0.f;
        int   cLS = 0,   cLD = 0;
        #pragma unroll
        for (int e = 0; e < 16; e++) {
            unsigned kk = fkey(x[e]);
            if ((cls >> e) & 1u) { if (kk < TS)  { sLS += x[e]; cLS++; } }
            else                 { if (~kk < TD) { sLD += x[e]; cLD++; } }
        }
        sLS = blockReduceF(sLS, fsh);
        sLD = blockReduceF(sLD, fsh);
        cLS = blockReduceI(cLS, ish);
        cLD = blockReduceI(cLD, ish);
        float simMinSum = sLS + (float)((int)qS - cLS) * finv(TS);
        float disMaxSum = sLD + (float)((int)qD - cLD) * finv(~TD);

        float similarMin    = simMinSum / (float)max((int)qS, 1);
        float dissimilarMax = disMaxSum / (float)max((int)qD, 1);
        float meanS  = fminf(fmaxf(sS / (float)max(ns, 1), 0.f), UPPERB);
        float meanDS = fminf(fmaxf(sD / (float)max(nd, 1), 0.f), UPPERB);

        float BP   = meanS  - (UPPERB - meanS) / UPPERB * fabsf(meanS - dissimilarMax);
        float BPds = meanDS - meanDS / UPPERB * fabsf(meanDS - similarMin);

        float dcf = CONST_BASE - CONST_C  * BP;
        float gcf = CONST_BASE - CONST_AC * BP;
        float d2  = CONST_BASE - CONST_C  * BPds;
        float g2  = CONST_BASE - CONST_AC * BPds;

        float pos = 0.f, nav = 0.f;
        #pragma unroll
        for (int e = 0; e < 16; e++) {
            float xv = x[e];
            if ((cls >> e) & 1u) {
                float f = (xv > BP) ? fmaf(CONST_C, xv, dcf) : fmaf(CONST_AC, xv, gcf);
                pos += softplusf(f);
            } else {
                float f = (xv < BPds) ? fmaf(CONST_C, xv, d2) : fmaf(CONST_AC, xv, g2);
                nav += softplusf(-f);
            }
        }
        pos = blockReduceF(pos, fsh);
        nav = blockReduceF(nav, fsh);
        rowres = pos / (float)max(ns, 1) + nav / (float)max(nd, 1);
    }

    if (tid == 0) {
        g_rowout[i] = make_float2(valid ? rowres : 0.f, valid ? 1.f : 0.f);
        __threadfence();
        unsigned old = atomicAdd(&g_ctr, 1u);
        lastFlag = (old == NPTS - 1) ? 1 : 0;
    }
    __syncthreads();

    if (lastFlag) {
        __threadfence();
        float t = 0.f, c = 0.f;
        for (int idx = tid; idx < NPTS; idx += RT) {
            float2 rv = g_rowout[idx];
            t += rv.x; c += rv.y;
        }
        t = blockReduceF(t, fsh);
        c = blockReduceF(c, fsh);
        if (tid == 0) out[0] = (c > 0.f) ? t / fmaxf(c, 1.f) : 0.f;
    }
}

// ---------------- launch ----------------
extern "C" void kernel_launch(void* const* d_in, const int* in_sizes, int n_in,
                              void* d_out, int out_size) {
    const float* u = (const float*)d_in[0];
    const float* v = (const float*)d_in[1];
    const int*   y = (const int*)d_in[2];

    mask_kernel<<<NPTS / 256, 256>>>(y);
    dim3 gg(NPTS / 128, NPTS / 128);
    gemm_kernel<<<gg, 256>>>(u, v);
    row_kernel<<<NPTS, RT>>>((float*)d_out);
}

// round 3
// speedup vs baseline: 1.3763x; 1.3763x over previous
#include <cuda_runtime.h>
#include <math.h>

#define NPTS 4096
#define BITD 64
#define LLAB 10
#define RT   256
#define UPPERB 16.0f
// c = (1/right)*ln(yp/(99(1-yp))) with right=64/6, yp=0.5  -> -6*ln(99)/64
#define CONST_C    (-0.43079248594386178f)
#define CONST_AC   (-0.86158497188772356f)   // a*c, a = 2 exactly
#define CONST_BASE (0.0f)

// ---------------- device scratch ----------------
__device__ float    g_inner[(size_t)NPTS * NPTS];   // 64 MB
__device__ unsigned g_maskArr[NPTS];
__device__ unsigned g_Ybits[LLAB * (NPTS / 32)];    // per-label membership bitvectors
__device__ float2   g_rowout[NPTS];                 // (rowres, valid)
__device__ unsigned g_ctr;

// ---------------- helpers ----------------
__device__ __forceinline__ unsigned fkey(float f) {
    unsigned u = __float_as_uint(f);
    return u ^ (((unsigned)((int)u >> 31)) | 0x80000000u);  // monotonic float->uint
}
__device__ __forceinline__ float finv(unsigned k) {
    unsigned u = (k & 0x80000000u) ? (k ^ 0x80000000u) : ~k;
    return __uint_as_float(u);
}
__device__ __forceinline__ float softplusf(float x) {
    return fmaxf(x, 0.f) + __logf(1.f + __expf(-fabsf(x)));
}

__device__ __forceinline__ float blockReduceF(float v, float* sh) {
    int tid = threadIdx.x, lane = tid & 31, wid = tid >> 5;
    #pragma unroll
    for (int o = 16; o > 0; o >>= 1) v += __shfl_down_sync(0xffffffffu, v, o);
    if (lane == 0) sh[wid] = v;
    __syncthreads();
    if (tid == 0) {
        float s = 0.f;
        #pragma unroll
        for (int w = 0; w < RT / 32; w++) s += sh[w];
        sh[0] = s;
    }
    __syncthreads();
    v = sh[0];
    __syncthreads();
    return v;
}
__device__ __forceinline__ int blockReduceI(int v, int* sh) {
    int tid = threadIdx.x, lane = tid & 31, wid = tid >> 5;
    #pragma unroll
    for (int o = 16; o > 0; o >>= 1) v += __shfl_down_sync(0xffffffffu, v, o);
    if (lane == 0) sh[wid] = v;
    __syncthreads();
    if (tid == 0) {
        int s = 0;
        #pragma unroll
        for (int w = 0; w < RT / 32; w++) s += sh[w];
        sh[0] = s;
    }
    __syncthreads();
    v = sh[0];
    __syncthreads();
    return v;
}

// ---------------- kernel 0: label bitmasks + per-label bitvectors ----------------
__global__ void mask_kernel(const int* __restrict__ y) {
    int j = blockIdx.x * blockDim.x + threadIdx.x;   // 4096 threads
    unsigned m = 0;
    #pragma unroll
    for (int l = 0; l < LLAB; l++) m |= (y[j * LLAB + l] != 0 ? 1u : 0u) << l;
    g_maskArr[j] = m;
    int word = j >> 5, lane = j & 31;
    #pragma unroll
    for (int b = 0; b < LLAB; b++) {
        unsigned bal = __ballot_sync(0xffffffffu, (m >> b) & 1u);
        if (lane == 0) g_Ybits[b * (NPTS / 32) + word] = bal;
    }
    if (j == 0) g_ctr = 0;
}

// ---------------- kernel 1: inner = U @ V^T (R1 layout: row-major smem) ----------------
#define TK   32
#define TPAD 36   // 32 + 4 pad; keeps float4 alignment, <=2-way LDS conflicts
__global__ void __launch_bounds__(256) gemm_kernel(const float* __restrict__ U,
                                                   const float* __restrict__ V) {
    __shared__ float As[128][TPAD];
    __shared__ float Bs[128][TPAD];
    int tid = threadIdx.x;
    int tx = tid & 15, ty = tid >> 4;       // 16 x 16 thread grid
    int brow = blockIdx.y * 128, bcol = blockIdx.x * 128;
    int lr = tid >> 3;                      // 0..31 (rows per load iter)
    int lc4 = tid & 7;                      // 0..7  (float4 within k-half)

    float acc[8][8];
    #pragma unroll
    for (int i = 0; i < 8; i++)
        #pragma unroll
        for (int j = 0; j < 8; j++) acc[i][j] = 0.f;

    for (int ks = 0; ks < BITD; ks += TK) {
        #pragma unroll
        for (int it = 0; it < 4; it++) {
            int r = it * 32 + lr;
            float4 a = *(const float4*)(U + (size_t)(brow + r) * BITD + ks + lc4 * 4);
            *(float4*)(&As[r][lc4 * 4]) = a;
            float4 b = *(const float4*)(V + (size_t)(bcol + r) * BITD + ks + lc4 * 4);
            *(float4*)(&Bs[r][lc4 * 4]) = b;
        }
        __syncthreads();
        #pragma unroll 4
        for (int k = 0; k < TK; k++) {
            float ar[8], bc[8];
            #pragma unroll
            for (int x = 0; x < 8; x++) ar[x] = As[ty * 8 + x][k];
            #pragma unroll
            for (int x = 0; x < 8; x++) bc[x] = Bs[tx + 16 * x][k];
            #pragma unroll
            for (int i = 0; i < 8; i++)
                #pragma unroll
                for (int j = 0; j < 8; j++) acc[i][j] = fmaf(ar[i], bc[j], acc[i][j]);
        }
        __syncthreads();
    }
    #pragma unroll
    for (int i = 0; i < 8; i++) {
        int row = brow + ty * 8 + i;
        #pragma unroll
        for (int j = 0; j < 8; j++)
            g_inner[(size_t)row * NPTS + bcol + tx + 16 * j] = acc[i][j];
    }
}

// ---------------- rank locate within a histogram ----------------
template<int BPT>
__device__ __forceinline__ void locate(const unsigned* hist, unsigned q,
                                       unsigned* wsum, unsigned* outBR) {
    int tid = threadIdx.x, lane = tid & 31, wid = tid >> 5;
    unsigned s = 0;
    int b0 = tid * BPT;
    #pragma unroll
    for (int t = 0; t < BPT; t++) s += hist[b0 + t];
    unsigned v = s;
    #pragma unroll
    for (int o = 1; o < 32; o <<= 1) {
        unsigned t = __shfl_up_sync(0xffffffffu, v, o);
        if (lane >= o) v += t;
    }
    if (lane == 31) wsum[wid] = v;
    __syncthreads();
    unsigned wb = 0;
    #pragma unroll
    for (int w = 0; w < RT / 32; w++) if (w < wid) wb += wsum[w];
    unsigned incl = wb + v, excl = incl - s;
    if (q > excl && q <= incl) {
        unsigned c = excl;
        #pragma unroll
        for (int t = 0; t < BPT; t++) {
            unsigned h = hist[b0 + t];
            if (q > c && q <= c + h) { outBR[0] = (unsigned)(b0 + t); outBR[1] = q - c; }
            c += h;
        }
    }
    __syncthreads();
}

// ---------------- kernel 2: per-row loss (+ fused final reduction) ----------------
__global__ void __launch_bounds__(RT, 4) row_kernel(float* __restrict__ out) {
    __shared__ unsigned histS[2048], histD[2048];
    __shared__ unsigned wsum[RT / 32];
    __shared__ float    fsh[RT / 32];
    __shared__ int      ish[RT / 32];
    __shared__ unsigned brS[2], brD[2];
    __shared__ int      lastFlag;

    int tid = threadIdx.x, i = blockIdx.x;

    for (int t = tid; t < 2048; t += RT) { histS[t] = 0u; histD[t] = 0u; }

    // class bits for my 16 contiguous elements [tid*16, tid*16+16)
    unsigned mi = g_maskArr[i];
    unsigned cls = 0;
    const unsigned short* yb = (const unsigned short*)g_Ybits;
    #pragma unroll
    for (int b = 0; b < LLAB; b++) {
        unsigned w = (unsigned)yb[b * (NPTS / 16) + tid];
        cls |= w & (0u - ((mi >> b) & 1u));
    }

    // load my 16 values into registers
    const float* rowp = g_inner + (size_t)i * NPTS + tid * 16;
    float x[16];
    #pragma unroll
    for (int q = 0; q < 4; q++) {
        float4 f = *(const float4*)(rowp + q * 4);
        x[q * 4 + 0] = f.x; x[q * 4 + 1] = f.y;
        x[q * 4 + 2] = f.z; x[q * 4 + 3] = f.w;
    }
    __syncthreads();   // hist cleared

    // pass 1: class sums + top-11-bit histograms
    float sS = 0.f, sD = 0.f;
    #pragma unroll
    for (int e = 0; e < 16; e++) {
        unsigned kk = fkey(x[e]);
        if ((cls >> e) & 1u) { sS += x[e]; atomicAdd(&histS[kk >> 21], 1u); }
        else                 { sD += x[e]; atomicAdd(&histD[(~kk) >> 21], 1u); }
    }
    int ns = blockReduceI(__popc(cls), ish);
    sS = blockReduceF(sS, fsh);
    sD = blockReduceF(sD, fsh);
    int nd = NPTS - ns;

    int ks = (ns * 9) / 10, kd = (nd * 9) / 10;
    unsigned qS = (unsigned)(ns - ks), qD = (unsigned)(nd - kd);
    bool valid = (ns > 0) && (nd > 0);

    float rowres = 0.f;
    if (valid) {
        locate<8>(histS, qS, wsum, brS);
        locate<8>(histD, qD, wsum, brD);
        unsigned b1S = brS[0], r1S = brS[1];
        unsigned b1D = brD[0], r1D = brD[1];

        // pass 2: middle 11 bits
        for (int t = tid; t < 2048; t += RT) { histS[t] = 0u; histD[t] = 0u; }
        __syncthreads();
        #pragma unroll
        for (int e = 0; e < 16; e++) {
            unsigned kk = fkey(x[e]);
            if ((cls >> e) & 1u) {
                if ((kk >> 21) == b1S) atomicAdd(&histS[(kk >> 10) & 2047u], 1u);
            } else {
                unsigned kd2 = ~kk;
                if ((kd2 >> 21) == b1D) atomicAdd(&histD[(kd2 >> 10) & 2047u], 1u);
            }
        }
        __syncthreads();
        locate<8>(histS, r1S, wsum, brS);
        locate<8>(histD, r1D, wsum, brD);
        unsigned b2S = brS[0], r2S = brS[1];
        unsigned b2D = brD[0], r2D = brD[1];
        unsigned p22S = (b1S << 11) | b2S;
        unsigned p22D = (b1D << 11) | b2D;

        // pass 3: low 10 bits
        for (int t = tid; t < 2048; t += RT) { histS[t] = 0u; histD[t] = 0u; }
        __syncthreads();
        #pragma unroll
        for (int e = 0; e < 16; e++) {
            unsigned kk = fkey(x[e]);
            if ((cls >> e) & 1u) {
                if ((kk >> 10) == p22S) atomicAdd(&histS[kk & 1023u], 1u);
            } else {
                unsigned kd2 = ~kk;
                if ((kd2 >> 10) == p22D) atomicAdd(&histD[kd2 & 1023u], 1u);
            }
        }
        __syncthreads();
        locate<4>(histS, r2S, wsum, brS);
        locate<4>(histD, r2D, wsum, brD);
        unsigned TS = (p22S << 10) | brS[0];
        unsigned TD = (p22D << 10) | brD[0];

        // final: exact sums below thresholds (register-only scan)
        float sLS = 0.f, sLD = 0.f;
        int   cLS = 0,   cLD = 0;
        #pragma unroll
        for (int e = 0; e < 16; e++) {
            unsigned kk = fkey(x[e]);
            if ((cls >> e) & 1u) { if (kk < TS)  { sLS += x[e]; cLS++; } }
            else                 { if (~kk < TD) { sLD += x[e]; cLD++; } }
        }
        sLS = blockReduceF(sLS, fsh);
        sLD = blockReduceF(sLD, fsh);
        cLS = blockReduceI(cLS, ish);
        cLD = blockReduceI(cLD, ish);
        float simMinSum = sLS + (float)((int)qS - cLS) * finv(TS);
        float disMaxSum = sLD + (float)((int)qD - cLD) * finv(~TD);

        float similarMin    = simMinSum / (float)max((int)qS, 1);
        float dissimilarMax = disMaxSum / (float)max((int)qD, 1);
        float meanS  = fminf(fmaxf(sS / (float)max(ns, 1), 0.f), UPPERB);
        float meanDS = fminf(fmaxf(sD / (float)max(nd, 1), 0.f), UPPERB);

        float BP   = meanS  - (UPPERB - meanS) / UPPERB * fabsf(meanS - dissimilarMax);
        float BPds = meanDS - meanDS / UPPERB * fabsf(meanDS - similarMin);

        float dcf = CONST_BASE - CONST_C  * BP;
        float gcf = CONST_BASE - CONST_AC * BP;
        float d2  = CONST_BASE - CONST_C  * BPds;
        float g2  = CONST_BASE - CONST_AC * BPds;

        float pos = 0.f, nav = 0.f;
        #pragma unroll
        for (int e = 0; e < 16; e++) {
            float xv = x[e];
            if ((cls >> e) & 1u) {
                float f = (xv > BP) ? fmaf(CONST_C, xv, dcf) : fmaf(CONST_AC, xv, gcf);
                pos += softplusf(f);
            } else {
                float f = (xv < BPds) ? fmaf(CONST_C, xv, d2) : fmaf(CONST_AC, xv, g2);
                nav += softplusf(-f);
            }
        }
        pos = blockReduceF(pos, fsh);
        nav = blockReduceF(nav, fsh);
        rowres = pos / (float)max(ns, 1) + nav / (float)max(nd, 1);
    }

    if (tid == 0) {
        g_rowout[i] = make_float2(valid ? rowres : 0.f, valid ? 1.f : 0.f);
        __threadfence();
        unsigned old = atomicAdd(&g_ctr, 1u);
        lastFlag = (old == NPTS - 1) ? 1 : 0;
    }
    __syncthreads();

    if (lastFlag) {
        __threadfence();
        float t = 0.f, c = 0.f;
        for (int idx = tid; idx < NPTS; idx += RT) {
            float2 rv = g_rowout[idx];
            t += rv.x; c += rv.y;
        }
        t = blockReduceF(t, fsh);
        c = blockReduceF(c, fsh);
        if (tid == 0) out[0] = (c > 0.f) ? t / fmaxf(c, 1.f) : 0.f;
    }
}

// ---------------- launch ----------------
extern "C" void kernel_launch(void* const* d_in, const int* in_sizes, int n_in,
                              void* d_out, int out_size) {
    const float* u = (const float*)d_in[0];
    const float* v = (const float*)d_in[1];
    const int*   y = (const int*)d_in[2];

    mask_kernel<<<NPTS / 256, 256>>>(y);
    dim3 gg(NPTS / 128, NPTS / 128);
    gemm_kernel<<<gg, 256>>>(u, v);
    row_kernel<<<NPTS, RT>>>((float*)d_out);
}